// round 8
// baseline (speedup 1.0000x reference)
#include <cuda_runtime.h>
#include <math.h>
#include <cstdint>

#define NN 50000
#define EE 800000
#define ALPHA_C 0.1f

// ---------------- scratch (device globals; no allocation allowed) ----------------
__device__ float g_t[NN * 128];
__device__ float g_h1[NN * 128];
__device__ float g_c[NN * 128];
__device__ float g_d1[NN];
__device__ float g_d2[NN];
__device__ int   g_cnt[NN];
__device__ int   g_off[NN + 1];
__device__ int   g_cur[NN];
__device__ int2  g_pk1[EE];
__device__ int2  g_pk2[EE];
__device__ int   g_is64;

// ---------------- dtype helpers ----------------
__device__ __forceinline__ int load_src(const void* ei, int e) {
    return g_is64 ? (int)((const long long*)ei)[e] : ((const int*)ei)[e];
}
__device__ __forceinline__ int load_dst(const void* ei, int e) {
    return g_is64 ? (int)((const long long*)ei)[EE + e] : ((const int*)ei)[EE + e];
}

// ---------------- prep: zero + dtype detect (merged) ----------------
__global__ void zero_detect_kernel(const int* ei32) {
    int i = blockIdx.x * blockDim.x + threadIdx.x;
    if (i < NN) { g_cnt[i] = 0; g_d2[i] = 1.0f; }
    if (blockIdx.x == 0) {
        __shared__ int any;
        if (threadIdx.x == 0) any = 0;
        __syncthreads();
        int local = 0;
        for (int k = threadIdx.x; k < 4096; k += blockDim.x)
            if (ei32[2 * k + 1] != 0) local = 1;
        if (local) atomicOr(&any, 1);
        __syncthreads();
        if (threadIdx.x == 0) g_is64 = (any == 0) ? 1 : 0;
    }
}

__global__ void count_kernel(const void* __restrict__ ei, const float* __restrict__ ew) {
    int e = blockIdx.x * blockDim.x + threadIdx.x;
    if (e >= EE) return;
    int d = load_dst(ei, e);
    atomicAdd(&g_cnt[d], 1);
    atomicAdd(&g_d2[d], ew[e]);
}

// single-block scan over counts -> offsets + cursors; also finalizes dinv1/dinv2
__global__ void scan_dinv_kernel() {
    __shared__ int tsum[1024];
    const int CH = (NN + 1023) / 1024;
    int t = threadIdx.x;
    int beg = t * CH, end = min(beg + CH, NN);
    int s = 0;
    for (int i = beg; i < end; i++) s += g_cnt[i];
    tsum[t] = s;
    __syncthreads();
    for (int off = 1; off < 1024; off <<= 1) {
        int v = (t >= off) ? tsum[t - off] : 0;
        __syncthreads();
        tsum[t] += v;
        __syncthreads();
    }
    int run = (t ? tsum[t - 1] : 0);
    for (int i = beg; i < end; i++) {
        int c = g_cnt[i];
        g_off[i] = run; g_cur[i] = run;
        run += c;
        g_d1[i] = rsqrtf(1.0f + (float)c);
        g_d2[i] = rsqrtf(g_d2[i]);
    }
    if (beg < NN && end == NN) g_off[NN] = run;
}

__global__ void fill_kernel(const void* __restrict__ ei, const float* __restrict__ ew) {
    int e = blockIdx.x * blockDim.x + threadIdx.x;
    if (e >= EE) return;
    int s = load_src(ei, e);
    int d = load_dst(ei, e);
    int pos = atomicAdd(&g_cur[d], 1);
    float w1 = g_d1[s];
    float w2 = g_d2[s] * ew[e];
    g_pk1[pos] = make_int2(s, __float_as_int(w1));
    g_pk2[pos] = make_int2(s, __float_as_int(w2));
}

// ---------------- GEMM: T[NN,C] = X[NN,128] @ W[128,C], C in {128,40} ----------------
// proven 64x64 tile, BK=32, 256 threads, 4x4 register tile (R2 config).
__global__ void gemm_kernel(const float* __restrict__ X, const float* __restrict__ W,
                            float* __restrict__ T, int C) {
    __shared__ float Xs[64][33];
    __shared__ float Ws[32][64];
    int tid  = threadIdx.x;
    int row0 = blockIdx.x * 64;
    int col0 = blockIdx.y * 64;
    int c0 = (tid & 15) * 4;
    int r0 = (tid >> 4) * 4;
    float acc[4][4] = {};

    for (int kk = 0; kk < 128; kk += 32) {
        #pragma unroll
        for (int f = tid; f < 512; f += 256) {
            int r = f >> 3, k4 = f & 7;
            int gr = row0 + r;
            float4 v = make_float4(0.f, 0.f, 0.f, 0.f);
            if (gr < NN) v = *(const float4*)(X + (size_t)gr * 128 + kk + k4 * 4);
            Xs[r][k4 * 4 + 0] = v.x; Xs[r][k4 * 4 + 1] = v.y;
            Xs[r][k4 * 4 + 2] = v.z; Xs[r][k4 * 4 + 3] = v.w;
        }
        #pragma unroll
        for (int f = tid; f < 512; f += 256) {
            int k = f >> 4, c4 = f & 15;
            int gc = col0 + c4 * 4;
            float4 v = make_float4(0.f, 0.f, 0.f, 0.f);
            if (gc < C) v = *(const float4*)(W + (size_t)(kk + k) * C + gc);
            *(float4*)&Ws[k][c4 * 4] = v;
        }
        __syncthreads();
        #pragma unroll
        for (int k = 0; k < 32; k++) {
            float4 w = *(const float4*)&Ws[k][c0];
            #pragma unroll
            for (int j = 0; j < 4; j++) {
                float xv = Xs[r0 + j][k];
                acc[j][0] += xv * w.x; acc[j][1] += xv * w.y;
                acc[j][2] += xv * w.z; acc[j][3] += xv * w.w;
            }
        }
        __syncthreads();
    }
    #pragma unroll
    for (int j = 0; j < 4; j++) {
        int gr = row0 + r0 + j;
        int gc = col0 + c0;
        if (gr < NN && gc < C)
            *(float4*)(T + (size_t)gr * C + gc) =
                make_float4(acc[j][0], acc[j][1], acc[j][2], acc[j][3]);
    }
}

// ---------------- fused CSR aggregation, 128-wide: TWO warps per dst node ----------------
// warp handles 64-feature half (float2 per lane); pk prefetch breaks the
// index->gather dependency chain.
__global__ void __launch_bounds__(256)
agg128_kernel(const float* __restrict__ T, float* __restrict__ OUT,
              const int2* __restrict__ pk,
              const float* __restrict__ dinv, const float* __restrict__ b,
              const float* __restrict__ H1, int mode) {
    int gw = (blockIdx.x * blockDim.x + threadIdx.x) >> 5;   // global warp id
    if (gw >= 2 * NN) return;
    int node = gw >> 1;
    int half = gw & 1;
    int lane = threadIdx.x & 31;
    int off  = half * 32 + lane;                 // float2 index within the 64-float2 row
    const float2* T2 = (const float2*)T;

    float dd = dinv[node];
    float2 acc = T2[(size_t)node * 64 + off];
    acc.x *= dd; acc.y *= dd;                    // self-loop term

    int i = g_off[node], end = g_off[node + 1];
    if (i < end) {
        int2 p = pk[i];
        while (true) {
            int2 pc = p;
            if (i + 1 < end) p = pk[i + 1];      // prefetch next slot
            float w = __int_as_float(pc.y);
            float2 v = T2[(size_t)pc.x * 64 + off];
            acc.x += v.x * w; acc.y += v.y * w;
            if (++i >= end) break;
        }
    }

    float2 bb = ((const float2*)b)[off];
    float rx = acc.x * dd + bb.x;
    float ry = acc.y * dd + bb.y;
    if (mode == 0) {
        rx = fmaxf(rx, 0.f); ry = fmaxf(ry, 0.f);
    } else {
        float2 h = ((const float2*)H1)[(size_t)node * 64 + off];
        rx += ALPHA_C * h.x; ry += ALPHA_C * h.y;
    }
    ((float2*)OUT)[(size_t)node * 64 + off] = make_float2(rx, ry);
}

// ---------------- fused CSR aggregation 40-wide + bias + log_softmax ----------------
__global__ void __launch_bounds__(256)
agg40_lsm_kernel(const float* __restrict__ T, float* __restrict__ OUT,
                 const int2* __restrict__ pk,
                 const float* __restrict__ dinv, const float* __restrict__ b) {
    int gw = (blockIdx.x * blockDim.x + threadIdx.x) >> 5;
    if (gw >= NN) return;
    int lane = threadIdx.x & 31;
    const float2* T2 = (const float2*)T;
    bool act = (lane < 20);
    int li = act ? lane : 0;

    float dd = dinv[gw];
    float2 acc;
    {
        float2 v = T2[(size_t)gw * 20 + li];
        acc.x = v.x * dd; acc.y = v.y * dd;
    }
    int i = g_off[gw], end = g_off[gw + 1];
    if (i < end) {
        int2 p = pk[i];
        while (true) {
            int2 pc = p;
            if (i + 1 < end) p = pk[i + 1];
            float w = __int_as_float(pc.y);
            float2 v = T2[(size_t)pc.x * 20 + li];
            acc.x += v.x * w; acc.y += v.y * w;
            if (++i >= end) break;
        }
    }
    float rx = -1e30f, ry = -1e30f;
    if (act) {
        float2 bb = ((const float2*)b)[lane];
        rx = acc.x * dd + bb.x;
        ry = acc.y * dd + bb.y;
    }
    float m = fmaxf(rx, ry);
    #pragma unroll
    for (int o = 16; o; o >>= 1) m = fmaxf(m, __shfl_xor_sync(0xffffffffu, m, o));
    float s_ = act ? (expf(rx - m) + expf(ry - m)) : 0.f;
    #pragma unroll
    for (int o = 16; o; o >>= 1) s_ += __shfl_xor_sync(0xffffffffu, s_, o);
    float l = m + logf(s_);
    if (act)
        ((float2*)OUT)[(size_t)gw * 20 + lane] = make_float2(rx - l, ry - l);
}

// ---------------- launch ----------------
extern "C" void kernel_launch(void* const* d_in, const int* in_sizes, int n_in,
                              void* d_out, int out_size) {
    const float* x  = (const float*)d_in[0];
    const void*  ei = d_in[1];
    const float* ew = (const float*)d_in[2];
    const float* W1 = (const float*)d_in[3];
    const float* b1 = (const float*)d_in[4];
    const float* W2 = (const float*)d_in[5];
    const float* b2 = (const float*)d_in[6];
    const float* W3 = (const float*)d_in[7];
    const float* b3 = (const float*)d_in[8];
    float* out = (float*)d_out;

    float *t, *h1, *c, *d1, *d2;
    int2 *pk1, *pk2;
    cudaGetSymbolAddress((void**)&t,   g_t);
    cudaGetSymbolAddress((void**)&h1,  g_h1);
    cudaGetSymbolAddress((void**)&c,   g_c);
    cudaGetSymbolAddress((void**)&d1,  g_d1);
    cudaGetSymbolAddress((void**)&d2,  g_d2);
    cudaGetSymbolAddress((void**)&pk1, g_pk1);
    cudaGetSymbolAddress((void**)&pk2, g_pk2);

    const int TB = 256;
    const int NB_N = (NN + TB - 1) / TB;
    const int NB_E = (EE + TB - 1) / TB;
    const int NB_W1 = (NN * 32 + TB - 1) / TB;       // one warp per node
    const int NB_W2 = (2 * NN * 32 + TB - 1) / TB;   // two warps per node
    dim3 gg128((NN + 63) / 64, 2);
    dim3 gg40((NN + 63) / 64, 1);

    // prep (6 launches); conv1 GEMM in slot 4 so ncu samples it
    zero_detect_kernel<<<NB_N, TB>>>((const int*)ei);
    count_kernel<<<NB_E, TB>>>(ei, ew);
    scan_dinv_kernel<<<1, 1024>>>();
    gemm_kernel<<<gg128, TB>>>(x, W1, t, 128);
    fill_kernel<<<NB_E, TB>>>(ei, ew);

    // conv1: h1 = relu(agg_1(x@W1) + b1)
    agg128_kernel<<<NB_W2, TB>>>(t, h1, pk1, d1, b1, nullptr, 0);

    // conv2 (crf): c = 0.1*h1 + agg_w(h1@W2) + b2
    gemm_kernel<<<gg128, TB>>>(h1, W2, t, 128);
    agg128_kernel<<<NB_W2, TB>>>(t, c, pk2, d2, b2, h1, 1);

    // conv3: out = log_softmax(agg_1(c@W3) + b3)
    gemm_kernel<<<gg40, TB>>>(c, W3, t, 40);
    agg40_lsm_kernel<<<NB_W1, TB>>>(t, out, pk1, d1, b3);
}

// round 9
// speedup vs baseline: 1.1008x; 1.1008x over previous
#include <cuda_runtime.h>
#include <cuda_fp16.h>
#include <math.h>
#include <cstdint>

#define NN 50000
#define EE 800000
#define ALPHA_C 0.1f

// ---------------- scratch (device globals; no allocation allowed) ----------------
__device__ __half g_t[NN * 128];   // GEMM output (fp16 message payload; also NN x 40)
__device__ float  g_h1[NN * 128];  // h1 (post relu, fp32)
__device__ float  g_c[NN * 128];   // combined h (fp32)
__device__ float  g_d1[NN];
__device__ float  g_d2[NN];
__device__ int    g_cnt[NN];
__device__ int    g_off[NN + 1];
__device__ int    g_cur[NN];
__device__ int2   g_pk1[EE];       // (src, bits(d1[src]))
__device__ int2   g_pk2[EE];       // (src, bits(d2[src]*ew))
__device__ int    g_is64;

// ---------------- dtype helpers ----------------
__device__ __forceinline__ int load_src(const void* ei, int e) {
    return g_is64 ? (int)((const long long*)ei)[e] : ((const int*)ei)[e];
}
__device__ __forceinline__ int load_dst(const void* ei, int e) {
    return g_is64 ? (int)((const long long*)ei)[EE + e] : ((const int*)ei)[EE + e];
}

// ---------------- prep: zero + dtype detect (merged) ----------------
__global__ void zero_detect_kernel(const int* ei32) {
    int i = blockIdx.x * blockDim.x + threadIdx.x;
    if (i < NN) { g_cnt[i] = 0; g_d2[i] = 1.0f; }
    if (blockIdx.x == 0) {
        __shared__ int any;
        if (threadIdx.x == 0) any = 0;
        __syncthreads();
        int local = 0;
        for (int k = threadIdx.x; k < 4096; k += blockDim.x)
            if (ei32[2 * k + 1] != 0) local = 1;
        if (local) atomicOr(&any, 1);
        __syncthreads();
        if (threadIdx.x == 0) g_is64 = (any == 0) ? 1 : 0;
    }
}

__global__ void count_kernel(const void* __restrict__ ei, const float* __restrict__ ew) {
    int e = blockIdx.x * blockDim.x + threadIdx.x;
    if (e >= EE) return;
    int d = load_dst(ei, e);
    atomicAdd(&g_cnt[d], 1);
    atomicAdd(&g_d2[d], ew[e]);
}

// single-block scan -> offsets + cursors; finalizes dinv1/dinv2
__global__ void scan_dinv_kernel() {
    __shared__ int tsum[1024];
    const int CH = (NN + 1023) / 1024;
    int t = threadIdx.x;
    int beg = t * CH, end = min(beg + CH, NN);
    int s = 0;
    for (int i = beg; i < end; i++) s += g_cnt[i];
    tsum[t] = s;
    __syncthreads();
    for (int off = 1; off < 1024; off <<= 1) {
        int v = (t >= off) ? tsum[t - off] : 0;
        __syncthreads();
        tsum[t] += v;
        __syncthreads();
    }
    int run = (t ? tsum[t - 1] : 0);
    for (int i = beg; i < end; i++) {
        int c = g_cnt[i];
        g_off[i] = run; g_cur[i] = run;
        run += c;
        g_d1[i] = rsqrtf(1.0f + (float)c);
        g_d2[i] = rsqrtf(g_d2[i]);
    }
    if (beg < NN && end == NN) g_off[NN] = run;
}

__global__ void fill_kernel(const void* __restrict__ ei, const float* __restrict__ ew) {
    int e = blockIdx.x * blockDim.x + threadIdx.x;
    if (e >= EE) return;
    int s = load_src(ei, e);
    int d = load_dst(ei, e);
    int pos = atomicAdd(&g_cur[d], 1);
    float w1 = g_d1[s];
    float w2 = g_d2[s] * ew[e];
    g_pk1[pos] = make_int2(s, __float_as_int(w1));
    g_pk2[pos] = make_int2(s, __float_as_int(w2));
}

// ---------------- GEMM: T[NN,C](fp16) = X[NN,128](fp32) @ W[128,C] ----------------
// proven 64x64 tile, BK=32, 256 threads, 4x4 register tile; fp32 acc, fp16 store.
__global__ void gemm_kernel(const float* __restrict__ X, const float* __restrict__ W,
                            __half* __restrict__ T, int C) {
    __shared__ float Xs[64][33];
    __shared__ float Ws[32][64];
    int tid  = threadIdx.x;
    int row0 = blockIdx.x * 64;
    int col0 = blockIdx.y * 64;
    int c0 = (tid & 15) * 4;
    int r0 = (tid >> 4) * 4;
    float acc[4][4] = {};

    for (int kk = 0; kk < 128; kk += 32) {
        #pragma unroll
        for (int f = tid; f < 512; f += 256) {
            int r = f >> 3, k4 = f & 7;
            int gr = row0 + r;
            float4 v = make_float4(0.f, 0.f, 0.f, 0.f);
            if (gr < NN) v = *(const float4*)(X + (size_t)gr * 128 + kk + k4 * 4);
            Xs[r][k4 * 4 + 0] = v.x; Xs[r][k4 * 4 + 1] = v.y;
            Xs[r][k4 * 4 + 2] = v.z; Xs[r][k4 * 4 + 3] = v.w;
        }
        #pragma unroll
        for (int f = tid; f < 512; f += 256) {
            int k = f >> 4, c4 = f & 15;
            int gc = col0 + c4 * 4;
            float4 v = make_float4(0.f, 0.f, 0.f, 0.f);
            if (gc < C) v = *(const float4*)(W + (size_t)(kk + k) * C + gc);
            *(float4*)&Ws[k][c4 * 4] = v;
        }
        __syncthreads();
        #pragma unroll
        for (int k = 0; k < 32; k++) {
            float4 w = *(const float4*)&Ws[k][c0];
            #pragma unroll
            for (int j = 0; j < 4; j++) {
                float xv = Xs[r0 + j][k];
                acc[j][0] += xv * w.x; acc[j][1] += xv * w.y;
                acc[j][2] += xv * w.z; acc[j][3] += xv * w.w;
            }
        }
        __syncthreads();
    }
    #pragma unroll
    for (int j = 0; j < 4; j++) {
        int gr = row0 + r0 + j;
        int gc = col0 + c0;
        if (gr < NN && gc < C) {
            __half2 h0 = __float22half2_rn(make_float2(acc[j][0], acc[j][1]));
            __half2 h1 = __float22half2_rn(make_float2(acc[j][2], acc[j][3]));
            uint2 u = make_uint2(*(uint32_t*)&h0, *(uint32_t*)&h1);
            // half index gr*C+gc, gc%4==0 -> uint2 aligned
            *(uint2*)(T + (size_t)gr * C + gc) = u;
        }
    }
}

// ---------------- fused CSR aggregation, 128-wide (one warp per node, fp16 gather) ----
// lane reads uint2 = 4 halves; row = 32 lanes x 8B = 256B (2 lines per edge).
__global__ void agg128_kernel(const __half* __restrict__ T, float* __restrict__ OUT,
                              const int2* __restrict__ pk,
                              const float* __restrict__ dinv, const float* __restrict__ b,
                              const float* __restrict__ H1, int mode) {
    int gw = (blockIdx.x * blockDim.x + threadIdx.x) >> 5;
    if (gw >= NN) return;
    int lane = threadIdx.x & 31;
    const uint2* Th = (const uint2*)T;   // 32 uint2 per 128-half row

    float dd = dinv[gw];
    float4 acc;
    {
        uint2 u = Th[(size_t)gw * 32 + lane];
        float2 a = __half22float2(*(__half2*)&u.x);
        float2 c = __half22float2(*(__half2*)&u.y);
        acc.x = a.x * dd; acc.y = a.y * dd;
        acc.z = c.x * dd; acc.w = c.y * dd;
    }

    int i = g_off[gw], end = g_off[gw + 1];
    for (; i < end; i++) {
        int2 p = pk[i];
        float w = __int_as_float(p.y);
        uint2 u = Th[(size_t)p.x * 32 + lane];
        float2 a = __half22float2(*(__half2*)&u.x);
        float2 c = __half22float2(*(__half2*)&u.y);
        acc.x += a.x * w; acc.y += a.y * w;
        acc.z += c.x * w; acc.w += c.y * w;
    }

    float4 bb = ((const float4*)b)[lane];
    float4 r;
    r.x = acc.x * dd + bb.x; r.y = acc.y * dd + bb.y;
    r.z = acc.z * dd + bb.z; r.w = acc.w * dd + bb.w;
    if (mode == 0) {
        r.x = fmaxf(r.x, 0.f); r.y = fmaxf(r.y, 0.f);
        r.z = fmaxf(r.z, 0.f); r.w = fmaxf(r.w, 0.f);
    } else {
        float4 h = ((const float4*)H1)[(size_t)gw * 32 + lane];
        r.x += ALPHA_C * h.x; r.y += ALPHA_C * h.y;
        r.z += ALPHA_C * h.z; r.w += ALPHA_C * h.w;
    }
    ((float4*)OUT)[(size_t)gw * 32 + lane] = r;
}

// ---------------- fused CSR aggregation 40-wide + bias + log_softmax (fp16 gather) ----
// lanes 0..19 read one half2 each (80B per row = 1 line per edge)
__global__ void agg40_lsm_kernel(const __half* __restrict__ T, float* __restrict__ OUT,
                                 const int2* __restrict__ pk,
                                 const float* __restrict__ dinv, const float* __restrict__ b) {
    int gw = (blockIdx.x * blockDim.x + threadIdx.x) >> 5;
    if (gw >= NN) return;
    int lane = threadIdx.x & 31;
    const uint32_t* Th = (const uint32_t*)T;   // 20 half2-words per 40-half row
    bool act = (lane < 20);
    int li = act ? lane : 0;

    float dd = dinv[gw];
    float2 acc;
    {
        uint32_t u = Th[(size_t)gw * 20 + li];
        float2 v = __half22float2(*(__half2*)&u);
        acc.x = v.x * dd; acc.y = v.y * dd;
    }
    int i = g_off[gw], end = g_off[gw + 1];
    for (; i < end; i++) {
        int2 p = pk[i];
        float w = __int_as_float(p.y);
        uint32_t u = Th[(size_t)p.x * 20 + li];
        float2 v = __half22float2(*(__half2*)&u);
        acc.x += v.x * w; acc.y += v.y * w;
    }
    float rx = -1e30f, ry = -1e30f;
    if (act) {
        float2 bb = ((const float2*)b)[lane];
        rx = acc.x * dd + bb.x;
        ry = acc.y * dd + bb.y;
    }
    float m = fmaxf(rx, ry);
    #pragma unroll
    for (int o = 16; o; o >>= 1) m = fmaxf(m, __shfl_xor_sync(0xffffffffu, m, o));
    float s_ = act ? (expf(rx - m) + expf(ry - m)) : 0.f;
    #pragma unroll
    for (int o = 16; o; o >>= 1) s_ += __shfl_xor_sync(0xffffffffu, s_, o);
    float l = m + logf(s_);
    if (act)
        ((float2*)OUT)[(size_t)gw * 20 + lane] = make_float2(rx - l, ry - l);
}

// ---------------- launch ----------------
extern "C" void kernel_launch(void* const* d_in, const int* in_sizes, int n_in,
                              void* d_out, int out_size) {
    const float* x  = (const float*)d_in[0];
    const void*  ei = d_in[1];
    const float* ew = (const float*)d_in[2];
    const float* W1 = (const float*)d_in[3];
    const float* b1 = (const float*)d_in[4];
    const float* W2 = (const float*)d_in[5];
    const float* b2 = (const float*)d_in[6];
    const float* W3 = (const float*)d_in[7];
    const float* b3 = (const float*)d_in[8];
    float* out = (float*)d_out;

    __half* t;
    float *h1, *c, *d1, *d2;
    int2 *pk1, *pk2;
    cudaGetSymbolAddress((void**)&t,   g_t);
    cudaGetSymbolAddress((void**)&h1,  g_h1);
    cudaGetSymbolAddress((void**)&c,   g_c);
    cudaGetSymbolAddress((void**)&d1,  g_d1);
    cudaGetSymbolAddress((void**)&d2,  g_d2);
    cudaGetSymbolAddress((void**)&pk1, g_pk1);
    cudaGetSymbolAddress((void**)&pk2, g_pk2);

    const int TB = 256;
    const int NB_N = (NN + TB - 1) / TB;
    const int NB_E = (EE + TB - 1) / TB;
    const int NB_W = (NN * 32 + TB - 1) / TB;   // one warp per node
    dim3 gg128((NN + 63) / 64, 2);
    dim3 gg40((NN + 63) / 64, 1);

    // prep; conv1 GEMM in slot 4 (ncu samples it)
    zero_detect_kernel<<<NB_N, TB>>>((const int*)ei);
    count_kernel<<<NB_E, TB>>>(ei, ew);
    scan_dinv_kernel<<<1, 1024>>>();
    gemm_kernel<<<gg128, TB>>>(x, W1, t, 128);
    fill_kernel<<<NB_E, TB>>>(ei, ew);

    // conv1: h1 = relu(agg_1(x@W1) + b1)
    agg128_kernel<<<NB_W, TB>>>(t, h1, pk1, d1, b1, nullptr, 0);

    // conv2 (crf): c = 0.1*h1 + agg_w(h1@W2) + b2
    gemm_kernel<<<gg128, TB>>>(h1, W2, t, 128);
    agg128_kernel<<<NB_W, TB>>>(t, c, pk2, d2, b2, h1, 1);

    // conv3: out = log_softmax(agg_1(c@W3) + b3)
    gemm_kernel<<<gg40, TB>>>(c, W3, t, 40);
    agg40_lsm_kernel<<<NB_W, TB>>>(t, out, pk1, d1, b3);
}